// round 3
// baseline (speedup 1.0000x reference)
#include <cuda_runtime.h>

// Loss_46883863003176: out = sum((pred - tgt)^2) / S / B
// pred, tgt: (4096, 2047, 2) float32, contiguous. Pure HBM-bound reduction.
// Two-pass: stage1 per-block partials -> __device__ scratch; stage2 final reduce
// overwrites d_out. No memset, no atomics, no allocations.

#ifndef BLOCK_THREADS
#define BLOCK_THREADS 256
#endif

#define NUM_BLOCKS (148 * 8)   // 1184 CTAs, 8 per SM

__device__ float g_partials[NUM_BLOCKS];

__global__ void __launch_bounds__(BLOCK_THREADS)
mse_stage1_kernel(const float4* __restrict__ pred,
                  const float4* __restrict__ tgt,
                  int n_vec4)
{
    const int tid     = threadIdx.x;
    const int gthread = blockIdx.x * BLOCK_THREADS + tid;
    const int stride  = gridDim.x * BLOCK_THREADS;

    float acc = 0.0f;

    // Unroll-by-2 grid-stride: 4 independent LDG.128 in flight per iteration.
    int i = gthread;
    for (; i + stride < n_vec4; i += 2 * stride) {
        float4 p0 = __ldg(&pred[i]);
        float4 t0 = __ldg(&tgt[i]);
        float4 p1 = __ldg(&pred[i + stride]);
        float4 t1 = __ldg(&tgt[i + stride]);

        float dx0 = p0.x - t0.x, dy0 = p0.y - t0.y;
        float dz0 = p0.z - t0.z, dw0 = p0.w - t0.w;
        acc = fmaf(dx0, dx0, acc);
        acc = fmaf(dy0, dy0, acc);
        acc = fmaf(dz0, dz0, acc);
        acc = fmaf(dw0, dw0, acc);

        float dx1 = p1.x - t1.x, dy1 = p1.y - t1.y;
        float dz1 = p1.z - t1.z, dw1 = p1.w - t1.w;
        acc = fmaf(dx1, dx1, acc);
        acc = fmaf(dy1, dy1, acc);
        acc = fmaf(dz1, dz1, acc);
        acc = fmaf(dw1, dw1, acc);
    }
    // Tail (at most one vector per thread)
    if (i < n_vec4) {
        float4 p = __ldg(&pred[i]);
        float4 t = __ldg(&tgt[i]);
        float dx = p.x - t.x, dy = p.y - t.y;
        float dz = p.z - t.z, dw = p.w - t.w;
        acc = fmaf(dx, dx, acc);
        acc = fmaf(dy, dy, acc);
        acc = fmaf(dz, dz, acc);
        acc = fmaf(dw, dw, acc);
    }

    // Warp reduce
    #pragma unroll
    for (int off = 16; off > 0; off >>= 1)
        acc += __shfl_xor_sync(0xFFFFFFFFu, acc, off);

    // Block reduce via shared
    __shared__ float warp_sums[BLOCK_THREADS / 32];
    const int lane = tid & 31;
    const int wid  = tid >> 5;
    if (lane == 0) warp_sums[wid] = acc;
    __syncthreads();

    if (wid == 0) {
        float v = (lane < BLOCK_THREADS / 32) ? warp_sums[lane] : 0.0f;
        #pragma unroll
        for (int off = 16; off > 0; off >>= 1)
            v += __shfl_xor_sync(0xFFFFFFFFu, v, off);
        if (lane == 0)
            g_partials[blockIdx.x] = v;
    }
}

__global__ void __launch_bounds__(1024)
mse_stage2_kernel(float* __restrict__ out, float inv_norm)
{
    const int tid = threadIdx.x;

    float acc = 0.0f;
    for (int i = tid; i < NUM_BLOCKS; i += 1024)
        acc += g_partials[i];

    // Warp reduce
    #pragma unroll
    for (int off = 16; off > 0; off >>= 1)
        acc += __shfl_xor_sync(0xFFFFFFFFu, acc, off);

    __shared__ float warp_sums[32];
    const int lane = tid & 31;
    const int wid  = tid >> 5;
    if (lane == 0) warp_sums[wid] = acc;
    __syncthreads();

    if (wid == 0) {
        float v = warp_sums[lane];   // 32 warps -> all lanes valid
        #pragma unroll
        for (int off = 16; off > 0; off >>= 1)
            v += __shfl_xor_sync(0xFFFFFFFFu, v, off);
        if (lane == 0)
            out[0] = v * inv_norm;   // overwrite poisoned d_out directly
    }
}

extern "C" void kernel_launch(void* const* d_in, const int* in_sizes, int n_in,
                              void* d_out, int out_size)
{
    const float* pred = (const float*)d_in[0];
    const float* tgt  = (const float*)d_in[1];
    float* out = (float*)d_out;

    const long long total = (long long)in_sizes[0];   // B * S * 2 = 16,769,024
    const int n_vec4 = (int)(total / 4);              // divisible by 4
    // normalizer: S * B = total / 2
    const float inv_norm = 2.0f / (float)total;

    mse_stage1_kernel<<<NUM_BLOCKS, BLOCK_THREADS>>>(
        (const float4*)pred, (const float4*)tgt, n_vec4);
    mse_stage2_kernel<<<1, 1024>>>(out, inv_norm);
}